// round 1
// baseline (speedup 1.0000x reference)
#include <cuda_runtime.h>
#include <cuda_bf16.h>
#include <math.h>

// ---------------------------------------------------------------------------
// Net: conv1(3->10,5x5) -> conv2(10->20,5x5) -> maxpool2 -> conv3(20->29,3x3)
//      -> permuted 1x1 (->14) -> flatten -> fc1 -> fc2 -> fc3 (all linear)
//
// Algebraic folding:
//   conv1+conv2  == single 9x9 conv 3->20  (both VALID, stride 1)
//   conv3..fc3   == single linear map  M[10][2880] + c[10]  on pooled [20,12,12]
// ---------------------------------------------------------------------------

#define NBATCH 8192

// scratch (device globals; no allocations allowed)
__device__ float g_Kc[3 * 9 * 9 * 20];   // combined conv weights, layout [ic][a][b][oc]
__device__ float g_bc[20];               // combined conv bias
__device__ float g_T[84 * 1400];         // fc2 @ fc1
__device__ float g_Wf[10 * 1400];        // fc3 @ fc2 @ fc1
__device__ float g_Wq[10 * 2900];        // after permuted-1x1 fold (per conv3-output-channel)
__device__ float g_M[2880 * 10];         // final folded matrix, layout [k][o]
__device__ float g_cbias[10];            // final folded bias

// ---------------------------------------------------------------------------
// Fold kernel 1: combined 9x9 conv weights + bias
// Kc[o,ic,a,b] = sum_m sum_{u+u'=a, v+v'=b} W2[o,m,u,v] * W1[m,ic,u',v']
// bc[o] = b2[o] + sum_m b1[m] * sum_{u,v} W2[o,m,u,v]
// ---------------------------------------------------------------------------
__global__ void k_combine_conv(const float* __restrict__ w1, const float* __restrict__ b1,
                               const float* __restrict__ w2, const float* __restrict__ b2) {
    int idx = blockIdx.x * blockDim.x + threadIdx.x;
    if (idx < 4860) {
        int o = idx / 243;
        int rem = idx % 243;
        int ic = rem / 81;
        int a = (rem % 81) / 9;
        int b = rem % 9;
        float val = 0.f;
        for (int m = 0; m < 10; m++) {
            for (int u = 0; u < 5; u++) {
                int ua = a - u;
                if (ua < 0 || ua > 4) continue;
                for (int v = 0; v < 5; v++) {
                    int vb = b - v;
                    if (vb < 0 || vb > 4) continue;
                    val += w2[((o * 10 + m) * 5 + u) * 5 + v] *
                           w1[((m * 3 + ic) * 5 + ua) * 5 + vb];
                }
            }
        }
        g_Kc[((ic * 9 + a) * 9 + b) * 20 + o] = val;
    } else if (idx < 4880) {
        int o = idx - 4860;
        float s = b2[o];
        for (int m = 0; m < 10; m++) {
            float ws = 0.f;
            for (int t = 0; t < 25; t++) ws += w2[(o * 10 + m) * 25 + t];
            s += b1[m] * ws;
        }
        g_bc[o] = s;
    }
}

// Fold kernel 2: T = fc2_w @ fc1_w   (84 x 1400)
__global__ void k_T(const float* __restrict__ fc1_w, const float* __restrict__ fc2_w) {
    int idx = blockIdx.x * blockDim.x + threadIdx.x;
    if (idx >= 84 * 1400) return;
    int j = idx / 1400, k = idx % 1400;
    float s = 0.f;
    for (int i = 0; i < 120; i++) s += fc2_w[j * 120 + i] * fc1_w[i * 1400 + k];
    g_T[idx] = s;
}

// Fold kernel 3: Wf = fc3_w @ T   (10 x 1400)
__global__ void k_Wf(const float* __restrict__ fc3_w) {
    int idx = blockIdx.x * blockDim.x + threadIdx.x;
    if (idx >= 10 * 1400) return;
    int o = idx / 1400, k = idx % 1400;
    float s = 0.f;
    for (int j = 0; j < 84; j++) s += fc3_w[o * 84 + j] * g_T[j * 1400 + k];
    g_Wf[idx] = s;
}

// Fold kernel 4: fold the permuted 1x1 conv.
// out feature j at spatial p uses conv3 channels {0, 2j+1, 2j+2}.
// Wq[o][ch*100+p]: coefficient of conv3-output[ch, p] in final output o.
__global__ void k_Wq(const float* __restrict__ p_w) {
    int idx = blockIdx.x * blockDim.x + threadIdx.x;
    if (idx >= 1000) return;
    int o = idx / 100, p = idx % 100;
    float s0 = 0.f;
    for (int j = 0; j < 14; j++) {
        float wf = g_Wf[o * 1400 + j * 100 + p];
        s0 += wf * p_w[j * 3 + 0];
        g_Wq[o * 2900 + (2 * j + 1) * 100 + p] = wf * p_w[j * 3 + 1];
        g_Wq[o * 2900 + (2 * j + 2) * 100 + p] = wf * p_w[j * 3 + 2];
    }
    g_Wq[o * 2900 + p] = s0;
}

// Fold kernel 5: fold conv3 (3x3, 20->29) into M[10][2880] (stored [k][o]).
// k indexes pooled tensor [ci][iy][ix] with iy,ix in [0,12).
__global__ void k_M(const float* __restrict__ w3) {
    int idx = blockIdx.x * blockDim.x + threadIdx.x;
    if (idx >= 28800) return;
    int o = idx / 2880, k = idx % 2880;
    int ci = k / 144;
    int iy = (k % 144) / 12;
    int ix = k % 12;
    float val = 0.f;
    for (int co = 0; co < 29; co++) {
        for (int ky = 0; ky < 3; ky++) {
            int oy = iy - ky;
            if (oy < 0 || oy >= 10) continue;
            for (int kx = 0; kx < 3; kx++) {
                int ox = ix - kx;
                if (ox < 0 || ox >= 10) continue;
                val += g_Wq[o * 2900 + co * 100 + oy * 10 + ox] *
                       w3[((co * 20 + ci) * 3 + ky) * 3 + kx];
            }
        }
    }
    g_M[k * 10 + o] = val;
}

// Fold kernel 6: final bias
__global__ void k_cbias(const float* __restrict__ fc1_b, const float* __restrict__ fc2_w,
                        const float* __restrict__ fc2_b, const float* __restrict__ fc3_w,
                        const float* __restrict__ fc3_b, const float* __restrict__ p_b,
                        const float* __restrict__ conv3_b) {
    int o = threadIdx.x;
    if (o >= 10) return;
    float bf = fc3_b[o];
    for (int j = 0; j < 84; j++) {
        float t = fc2_b[j];
        for (int i = 0; i < 120; i++) t += fc2_w[j * 120 + i] * fc1_b[i];
        bf += fc3_w[o * 84 + j] * t;
    }
    for (int j = 0; j < 14; j++) {
        float s = 0.f;
        for (int p = 0; p < 100; p++) s += g_Wf[o * 1400 + j * 100 + p];
        bf += p_b[j] * s;
    }
    for (int co = 0; co < 29; co++) {
        float s = 0.f;
        for (int p = 0; p < 100; p++) s += g_Wq[o * 2900 + co * 100 + p];
        bf += conv3_b[co] * s;
    }
    g_cbias[o] = bf;
}

// ---------------------------------------------------------------------------
// Main fused kernel: per image — 9x9 conv (3->20) + bias + 2x2 maxpool, then
// dot with folded M[2880][10] + c.
// 288 threads = 144 pooled positions x 2 channel-groups (10 ch each).
// ---------------------------------------------------------------------------
__global__ void __launch_bounds__(288) k_main(const float* __restrict__ x,
                                              float* __restrict__ out) {
    __shared__ float xs[3 * 32 * 32];   // input image
    __shared__ float ws[4860];          // combined weights [ic][a][b][oc]
    __shared__ float red[9][10];        // per-warp partials

    int b = blockIdx.x;
    int tid = threadIdx.x;
    const float* xb = x + (size_t)b * 3072;
    for (int i = tid; i < 3072; i += 288) xs[i] = xb[i];
    for (int i = tid; i < 4860; i += 288) ws[i] = g_Kc[i];
    __syncthreads();

    int pos = tid % 144;            // pooled spatial position
    int grp = tid / 144;            // channel half (0: ch0-9, 1: ch10-19)
    int py = pos / 12, px = pos % 12;
    int oy = py * 2, ox = px * 2;   // top-left conv position of the pool window

    float a0[10], a1[10], a2[10], a3[10];
#pragma unroll
    for (int c = 0; c < 10; c++) { a0[c] = 0.f; a1[c] = 0.f; a2[c] = 0.f; a3[c] = 0.f; }

#pragma unroll 1
    for (int ic = 0; ic < 3; ic++) {
#pragma unroll 1
        for (int ky = 0; ky < 9; ky++) {
            const float* r0 = &xs[ic * 1024 + (oy + ky) * 32 + ox];
            const float* r1 = r0 + 32;
            float x0[10], x1[10];
#pragma unroll
            for (int t = 0; t < 10; t++) { x0[t] = r0[t]; x1[t] = r1[t]; }
            const float* wbase = &ws[((ic * 9 + ky) * 9) * 20 + grp * 10];
#pragma unroll
            for (int kx = 0; kx < 9; kx++) {
                const float* wp = wbase + kx * 20;
#pragma unroll
                for (int c = 0; c < 10; c++) {
                    float w = wp[c];
                    a0[c] += w * x0[kx];
                    a1[c] += w * x0[kx + 1];
                    a2[c] += w * x1[kx];
                    a3[c] += w * x1[kx + 1];
                }
            }
        }
    }

    // bias + maxpool
    float po[10];
#pragma unroll
    for (int c = 0; c < 10; c++) {
        float m = fmaxf(fmaxf(a0[c], a1[c]), fmaxf(a2[c], a3[c]));
        po[c] = m + g_bc[grp * 10 + c];
    }

    // partial dot with folded matrix
    float oa[10];
#pragma unroll
    for (int o = 0; o < 10; o++) oa[o] = 0.f;
#pragma unroll 1
    for (int c = 0; c < 10; c++) {
        const float* Mr = &g_M[((grp * 10 + c) * 144 + pos) * 10];
        float p = po[c];
#pragma unroll
        for (int o = 0; o < 10; o++) oa[o] += Mr[o] * p;
    }

    // warp reduce
#pragma unroll
    for (int o = 0; o < 10; o++) {
#pragma unroll
        for (int off = 16; off > 0; off >>= 1)
            oa[o] += __shfl_xor_sync(0xffffffffu, oa[o], off);
    }
    int wid = tid / 32, lane = tid % 32;
    if (lane == 0) {
#pragma unroll
        for (int o = 0; o < 10; o++) red[wid][o] = oa[o];
    }
    __syncthreads();
    if (tid < 10) {
        float s = g_cbias[tid];
#pragma unroll
        for (int w = 0; w < 9; w++) s += red[w][tid];
        out[(size_t)b * 10 + tid] = s;
    }
}

// ---------------------------------------------------------------------------
extern "C" void kernel_launch(void* const* d_in, const int* in_sizes, int n_in,
                              void* d_out, int out_size) {
    const float* x       = (const float*)d_in[0];
    const float* conv1_w = (const float*)d_in[1];
    const float* conv1_b = (const float*)d_in[2];
    const float* conv2_w = (const float*)d_in[3];
    const float* conv2_b = (const float*)d_in[4];
    const float* conv3_w = (const float*)d_in[5];
    const float* conv3_b = (const float*)d_in[6];
    const float* p_w     = (const float*)d_in[7];
    const float* p_b     = (const float*)d_in[8];
    const float* fc1_w   = (const float*)d_in[9];
    const float* fc1_b   = (const float*)d_in[10];
    const float* fc2_w   = (const float*)d_in[11];
    const float* fc2_b   = (const float*)d_in[12];
    const float* fc3_w   = (const float*)d_in[13];
    const float* fc3_b   = (const float*)d_in[14];
    float* out = (float*)d_out;

    k_combine_conv<<<(4880 + 127) / 128, 128>>>(conv1_w, conv1_b, conv2_w, conv2_b);
    k_T<<<(84 * 1400 + 255) / 256, 256>>>(fc1_w, fc2_w);
    k_Wf<<<(14000 + 255) / 256, 256>>>(fc3_w);
    k_Wq<<<4, 256>>>(p_w);
    k_M<<<(28800 + 255) / 256, 256>>>(conv3_w);
    k_cbias<<<1, 32>>>(fc1_b, fc2_w, fc2_b, fc3_w, fc3_b, p_b, conv3_b);
    k_main<<<NBATCH, 288>>>(x, out);
}

// round 2
// speedup vs baseline: 1.0812x; 1.0812x over previous
#include <cuda_runtime.h>
#include <cuda_bf16.h>
#include <math.h>

// ---------------------------------------------------------------------------
// Net: conv1(3->10,5x5) -> conv2(10->20,5x5) -> maxpool2 -> conv3(20->29,3x3)
//      -> permuted 1x1 (->14) -> flatten -> fc1 -> fc2 -> fc3 (all linear)
//
// Folding:
//   conv1+conv2  == single 9x9 conv 3->20
//   conv3..fc3   == single linear map  M[10][2880] + c[10]  on pooled [20,12,12]
// Round 2: conv inner loop on packed fma.rn.f32x2 (Blackwell 2x fp32 path).
// ---------------------------------------------------------------------------

#define NBATCH 8192

typedef unsigned long long u64;

// scratch (device globals; no allocations allowed)
__device__ float2 g_Kc2[3 * 9 * 9 * 20]; // combined conv weights, duplicated {w,w}, [ic][a][b][oc]
__device__ float g_bc[20];               // combined conv bias
__device__ float g_T[84 * 1400];         // fc2 @ fc1
__device__ float g_Wf[10 * 1400];        // fc3 @ fc2 @ fc1
__device__ float g_Wq[10 * 2900];        // after permuted-1x1 fold
__device__ float g_M[2880 * 10];         // final folded matrix, layout [k][o]
__device__ float g_cbias[10];            // final folded bias

// ---- f32x2 helpers --------------------------------------------------------
__device__ __forceinline__ u64 pack2(float lo, float hi) {
    u64 r;
    asm("mov.b64 %0, {%1, %2};" : "=l"(r) : "f"(lo), "f"(hi));
    return r;
}
__device__ __forceinline__ void unpack2(u64 v, float& lo, float& hi) {
    asm("mov.b64 {%0, %1}, %2;" : "=f"(lo), "=f"(hi) : "l"(v));
}
__device__ __forceinline__ u64 ffma2(u64 a, u64 b, u64 c) {
    u64 d;
    asm("fma.rn.f32x2 %0, %1, %2, %3;" : "=l"(d) : "l"(a), "l"(b), "l"(c));
    return d;
}

// ---------------------------------------------------------------------------
// Fold kernel 1: combined 9x9 conv weights (duplicated pairs) + bias
// ---------------------------------------------------------------------------
__global__ void k_combine_conv(const float* __restrict__ w1, const float* __restrict__ b1,
                               const float* __restrict__ w2, const float* __restrict__ b2) {
    int idx = blockIdx.x * blockDim.x + threadIdx.x;
    if (idx < 4860) {
        int o = idx / 243;
        int rem = idx % 243;
        int ic = rem / 81;
        int a = (rem % 81) / 9;
        int b = rem % 9;
        float val = 0.f;
        for (int m = 0; m < 10; m++) {
            for (int u = 0; u < 5; u++) {
                int ua = a - u;
                if (ua < 0 || ua > 4) continue;
                for (int v = 0; v < 5; v++) {
                    int vb = b - v;
                    if (vb < 0 || vb > 4) continue;
                    val += w2[((o * 10 + m) * 5 + u) * 5 + v] *
                           w1[((m * 3 + ic) * 5 + ua) * 5 + vb];
                }
            }
        }
        g_Kc2[((ic * 9 + a) * 9 + b) * 20 + o] = make_float2(val, val);
    } else if (idx < 4880) {
        int o = idx - 4860;
        float s = b2[o];
        for (int m = 0; m < 10; m++) {
            float ws = 0.f;
            for (int t = 0; t < 25; t++) ws += w2[(o * 10 + m) * 25 + t];
            s += b1[m] * ws;
        }
        g_bc[o] = s;
    }
}

// Fold kernel 2: T = fc2_w @ fc1_w   (84 x 1400)
__global__ void k_T(const float* __restrict__ fc1_w, const float* __restrict__ fc2_w) {
    int idx = blockIdx.x * blockDim.x + threadIdx.x;
    if (idx >= 84 * 1400) return;
    int j = idx / 1400, k = idx % 1400;
    float s = 0.f;
    for (int i = 0; i < 120; i++) s += fc2_w[j * 120 + i] * fc1_w[i * 1400 + k];
    g_T[idx] = s;
}

// Fold kernel 3: Wf = fc3_w @ T   (10 x 1400)
__global__ void k_Wf(const float* __restrict__ fc3_w) {
    int idx = blockIdx.x * blockDim.x + threadIdx.x;
    if (idx >= 10 * 1400) return;
    int o = idx / 1400, k = idx % 1400;
    float s = 0.f;
    for (int j = 0; j < 84; j++) s += fc3_w[o * 84 + j] * g_T[j * 1400 + k];
    g_Wf[idx] = s;
}

// Fold kernel 4: fold the permuted 1x1 conv.
__global__ void k_Wq(const float* __restrict__ p_w) {
    int idx = blockIdx.x * blockDim.x + threadIdx.x;
    if (idx >= 1000) return;
    int o = idx / 100, p = idx % 100;
    float s0 = 0.f;
    for (int j = 0; j < 14; j++) {
        float wf = g_Wf[o * 1400 + j * 100 + p];
        s0 += wf * p_w[j * 3 + 0];
        g_Wq[o * 2900 + (2 * j + 1) * 100 + p] = wf * p_w[j * 3 + 1];
        g_Wq[o * 2900 + (2 * j + 2) * 100 + p] = wf * p_w[j * 3 + 2];
    }
    g_Wq[o * 2900 + p] = s0;
}

// Fold kernel 5: fold conv3 (3x3, 20->29) into M[10][2880] (stored [k][o]).
__global__ void k_M(const float* __restrict__ w3) {
    int idx = blockIdx.x * blockDim.x + threadIdx.x;
    if (idx >= 28800) return;
    int o = idx / 2880, k = idx % 2880;
    int ci = k / 144;
    int iy = (k % 144) / 12;
    int ix = k % 12;
    float val = 0.f;
    for (int co = 0; co < 29; co++) {
        for (int ky = 0; ky < 3; ky++) {
            int oy = iy - ky;
            if (oy < 0 || oy >= 10) continue;
            for (int kx = 0; kx < 3; kx++) {
                int ox = ix - kx;
                if (ox < 0 || ox >= 10) continue;
                val += g_Wq[o * 2900 + co * 100 + oy * 10 + ox] *
                       w3[((co * 20 + ci) * 3 + ky) * 3 + kx];
            }
        }
    }
    g_M[k * 10 + o] = val;
}

// Fold kernel 6: final bias
__global__ void k_cbias(const float* __restrict__ fc1_b, const float* __restrict__ fc2_w,
                        const float* __restrict__ fc2_b, const float* __restrict__ fc3_w,
                        const float* __restrict__ fc3_b, const float* __restrict__ p_b,
                        const float* __restrict__ conv3_b) {
    int o = threadIdx.x;
    if (o >= 10) return;
    float bf = fc3_b[o];
    for (int j = 0; j < 84; j++) {
        float t = fc2_b[j];
        for (int i = 0; i < 120; i++) t += fc2_w[j * 120 + i] * fc1_b[i];
        bf += fc3_w[o * 84 + j] * t;
    }
    for (int j = 0; j < 14; j++) {
        float s = 0.f;
        for (int p = 0; p < 100; p++) s += g_Wf[o * 1400 + j * 100 + p];
        bf += p_b[j] * s;
    }
    for (int co = 0; co < 29; co++) {
        float s = 0.f;
        for (int p = 0; p < 100; p++) s += g_Wq[o * 2900 + co * 100 + p];
        bf += conv3_b[co] * s;
    }
    g_cbias[o] = bf;
}

// ---------------------------------------------------------------------------
// Main fused kernel: per image — 9x9 conv (3->20) + bias + 2x2 maxpool, then
// dot with folded M[2880][10] + c.  Conv inner loop on fma.rn.f32x2:
// (a0,a1) and (a2,a3) pool candidates share each weight, packed as f32x2.
// 288 threads = 144 pooled positions x 2 channel-groups (10 ch each).
// ---------------------------------------------------------------------------
__global__ void __launch_bounds__(288) k_main(const float* __restrict__ x,
                                              float* __restrict__ out) {
    __shared__ float xs[3 * 32 * 32];   // input image
    __shared__ u64 ws2[4860];           // duplicated weights {w,w}, [ic][a][b][oc]
    __shared__ float red[9][10];        // per-warp partials

    int b = blockIdx.x;
    int tid = threadIdx.x;

    // cooperative loads (vectorized)
    {
        const float4* xb4 = (const float4*)(x + (size_t)b * 3072);
        float4* xs4 = (float4*)xs;
        for (int i = tid; i < 768; i += 288) xs4[i] = xb4[i];
        const u64* src = (const u64*)g_Kc2;
        for (int i = tid; i < 4860; i += 288) ws2[i] = src[i];
    }
    __syncthreads();

    int pos = tid % 144;            // pooled spatial position
    int grp = tid / 144;            // channel half (0: ch0-9, 1: ch10-19)
    int py = pos / 12, px = pos % 12;
    int oy = py * 2, ox = px * 2;   // top-left conv position of the pool window

    u64 acc01[10], acc23[10];
#pragma unroll
    for (int c = 0; c < 10; c++) { acc01[c] = 0ull; acc23[c] = 0ull; }

#pragma unroll 1
    for (int ic = 0; ic < 3; ic++) {
#pragma unroll 1
        for (int ky = 0; ky < 9; ky++) {
            const float* r0 = &xs[ic * 1024 + (oy + ky) * 32 + ox];
            const float* r1 = r0 + 32;
            float x0[10], x1[10];
#pragma unroll
            for (int t = 0; t < 10; t++) { x0[t] = r0[t]; x1[t] = r1[t]; }
            const u64* wrow = &ws2[((ic * 9 + ky) * 9) * 20 + grp * 10];
#pragma unroll
            for (int kx = 0; kx < 9; kx++) {
                u64 xp0 = pack2(x0[kx], x0[kx + 1]);
                u64 xp1 = pack2(x1[kx], x1[kx + 1]);
                const u64* wp = wrow + kx * 20;
#pragma unroll
                for (int c = 0; c < 10; c++) {
                    u64 w = wp[c];
                    acc01[c] = ffma2(w, xp0, acc01[c]);
                    acc23[c] = ffma2(w, xp1, acc23[c]);
                }
            }
        }
    }

    // unpack + bias + maxpool
    float po[10];
#pragma unroll
    for (int c = 0; c < 10; c++) {
        float a0, a1, a2, a3;
        unpack2(acc01[c], a0, a1);
        unpack2(acc23[c], a2, a3);
        float m = fmaxf(fmaxf(a0, a1), fmaxf(a2, a3));
        po[c] = m + g_bc[grp * 10 + c];
    }

    // partial dot with folded matrix
    float oa[10];
#pragma unroll
    for (int o = 0; o < 10; o++) oa[o] = 0.f;
#pragma unroll 1
    for (int c = 0; c < 10; c++) {
        const float* Mr = &g_M[((grp * 10 + c) * 144 + pos) * 10];
        float p = po[c];
#pragma unroll
        for (int o = 0; o < 10; o++) oa[o] += Mr[o] * p;
    }

    // warp reduce
#pragma unroll
    for (int o = 0; o < 10; o++) {
#pragma unroll
        for (int off = 16; off > 0; off >>= 1)
            oa[o] += __shfl_xor_sync(0xffffffffu, oa[o], off);
    }
    int wid = tid / 32, lane = tid % 32;
    if (lane == 0) {
#pragma unroll
        for (int o = 0; o < 10; o++) red[wid][o] = oa[o];
    }
    __syncthreads();
    if (tid < 10) {
        float s = g_cbias[tid];
#pragma unroll
        for (int w = 0; w < 9; w++) s += red[w][tid];
        out[(size_t)b * 10 + tid] = s;
    }
}

// ---------------------------------------------------------------------------
extern "C" void kernel_launch(void* const* d_in, const int* in_sizes, int n_in,
                              void* d_out, int out_size) {
    const float* x       = (const float*)d_in[0];
    const float* conv1_w = (const float*)d_in[1];
    const float* conv1_b = (const float*)d_in[2];
    const float* conv2_w = (const float*)d_in[3];
    const float* conv2_b = (const float*)d_in[4];
    const float* conv3_w = (const float*)d_in[5];
    const float* conv3_b = (const float*)d_in[6];
    const float* p_w     = (const float*)d_in[7];
    const float* p_b     = (const float*)d_in[8];
    const float* fc1_w   = (const float*)d_in[9];
    const float* fc1_b   = (const float*)d_in[10];
    const float* fc2_w   = (const float*)d_in[11];
    const float* fc2_b   = (const float*)d_in[12];
    const float* fc3_w   = (const float*)d_in[13];
    const float* fc3_b   = (const float*)d_in[14];
    float* out = (float*)d_out;

    k_combine_conv<<<(4880 + 127) / 128, 128>>>(conv1_w, conv1_b, conv2_w, conv2_b);
    k_T<<<(84 * 1400 + 255) / 256, 256>>>(fc1_w, fc2_w);
    k_Wf<<<(14000 + 255) / 256, 256>>>(fc3_w);
    k_Wq<<<4, 256>>>(p_w);
    k_M<<<(28800 + 255) / 256, 256>>>(conv3_w);
    k_cbias<<<1, 32>>>(fc1_b, fc2_w, fc2_b, fc3_w, fc3_b, p_b, conv3_b);
    k_main<<<NBATCH, 288>>>(x, out);
}

// round 3
// speedup vs baseline: 1.2544x; 1.1602x over previous
#include <cuda_runtime.h>
#include <cuda_bf16.h>
#include <math.h>

// ---------------------------------------------------------------------------
// Net: conv1(3->10,5x5) -> conv2(10->20,5x5) -> maxpool2 -> conv3(20->29,3x3)
//      -> permuted 1x1 (->14) -> flatten -> fc1 -> fc2 -> fc3 (all linear)
//
// Folding:
//   conv1+conv2  == single 9x9 conv 3->20  (K=243 im2col)
//   conv3..fc3   == single linear map  M[10][2880] + c[10]  on pooled [20,12,12]
// Round 3: conv on tensor cores (mma.sync m16n8k16 bf16), fp32 emulated via
//          3-term bf16 split (hi*hi + hi*lo + lo*hi). K layout: ky-major,
//          per-ky 32 slots (ic*10+kx, kx<9 real, rest zero-weight padded).
// ---------------------------------------------------------------------------

typedef unsigned int u32;
typedef unsigned short u16;

// ---- device scratch (no allocations allowed) ------------------------------
__device__ float g_Kc[3 * 9 * 9 * 20];   // combined conv weights [ic][ky][kx][oc]
__device__ float g_bc[20];               // combined conv bias
__device__ float g_T[84 * 1400];         // fc2 @ fc1
__device__ float g_Wf[10 * 1400];        // fc3 @ fc2 @ fc1
__device__ float g_Wq[10 * 2900];        // after permuted-1x1 fold
__device__ float g_M[2880 * 10];         // final folded matrix, layout [k][o]
__device__ float g_cbias[10];            // final folded bias
__device__ u32 g_BpHi[9 * 16 * 24];      // bf16x2 weight pairs (hi), [ky][pair][oc]
__device__ u32 g_BpLo[9 * 16 * 24];      // bf16x2 weight pairs (lo)

// ---- helpers --------------------------------------------------------------
__device__ __forceinline__ u16 f2bf_bits(float v) {
    __nv_bfloat16 h = __float2bfloat16(v);
    return *(u16*)&h;
}
__device__ __forceinline__ float bf2f(u16 b) {
    __nv_bfloat16 h = *(__nv_bfloat16*)&b;
    return __bfloat162float(h);
}

__device__ __forceinline__ void mma16816(float* d, const u32* a, u32 b0, u32 b1) {
    asm volatile(
        "mma.sync.aligned.m16n8k16.row.col.f32.bf16.bf16.f32 "
        "{%0,%1,%2,%3}, {%4,%5,%6,%7}, {%8,%9}, {%0,%1,%2,%3};"
        : "+f"(d[0]), "+f"(d[1]), "+f"(d[2]), "+f"(d[3])
        : "r"(a[0]), "r"(a[1]), "r"(a[2]), "r"(a[3]), "r"(b0), "r"(b1));
}

// ---------------------------------------------------------------------------
// Fold A: T = fc2_w @ fc1_w  AND  combined 9x9 conv weights + bias
// ---------------------------------------------------------------------------
__global__ void kA_T_combine(const float* __restrict__ fc1_w, const float* __restrict__ fc2_w,
                             const float* __restrict__ w1, const float* __restrict__ b1,
                             const float* __restrict__ w2, const float* __restrict__ b2) {
    int idx = blockIdx.x * blockDim.x + threadIdx.x;
    if (idx < 117600) {
        int j = idx / 1400, k = idx % 1400;
        float s = 0.f;
        for (int i = 0; i < 120; i++) s += fc2_w[j * 120 + i] * fc1_w[i * 1400 + k];
        g_T[idx] = s;
    } else if (idx < 117600 + 4860) {
        int t = idx - 117600;
        int o = t / 243;
        int rem = t % 243;
        int ic = rem / 81;
        int a = (rem % 81) / 9;
        int b = rem % 9;
        float val = 0.f;
        for (int m = 0; m < 10; m++) {
            for (int u = 0; u < 5; u++) {
                int ua = a - u;
                if (ua < 0 || ua > 4) continue;
                for (int v = 0; v < 5; v++) {
                    int vb = b - v;
                    if (vb < 0 || vb > 4) continue;
                    val += w2[((o * 10 + m) * 5 + u) * 5 + v] *
                           w1[((m * 3 + ic) * 5 + ua) * 5 + vb];
                }
            }
        }
        g_Kc[((ic * 9 + a) * 9 + b) * 20 + o] = val;
    } else if (idx < 117600 + 4880) {
        int o = idx - 117600 - 4860;
        float s = b2[o];
        for (int m = 0; m < 10; m++) {
            float ws = 0.f;
            for (int t = 0; t < 25; t++) ws += w2[(o * 10 + m) * 25 + t];
            s += b1[m] * ws;
        }
        g_bc[o] = s;
    }
}

// ---------------------------------------------------------------------------
// Fold B: Wf = fc3_w @ T  AND  bf16 weight pair tables (hi/lo split)
// Per-ky K layout: k'' in [0,32): ic = k''/10, kx = k''%10; zero if kx==9,
// k''>=30, or oc>=20.  Pair p packs (k''=2p, 2p+1) into one bf16x2 u32.
// ---------------------------------------------------------------------------
__global__ void kB_Wf_Bpair(const float* __restrict__ fc3_w) {
    int idx = blockIdx.x * blockDim.x + threadIdx.x;
    if (idx < 14000) {
        int o = idx / 1400, k = idx % 1400;
        float s = 0.f;
        for (int j = 0; j < 84; j++) s += fc3_w[o * 84 + j] * g_T[j * 1400 + k];
        g_Wf[idx] = s;
    } else if (idx < 14000 + 3456) {
        int j = idx - 14000;
        int oc = j % 24;
        int p = (j / 24) % 16;
        int ky = j / (24 * 16);
        float v[2];
        for (int h = 0; h < 2; h++) {
            int k2 = 2 * p + h;
            float val = 0.f;
            if (oc < 20 && k2 < 30) {
                int ic = k2 / 10, kx = k2 % 10;
                if (kx < 9) val = g_Kc[((ic * 9 + ky) * 9 + kx) * 20 + oc];
            }
            v[h] = val;
        }
        u16 h0 = f2bf_bits(v[0]), h1 = f2bf_bits(v[1]);
        float r0 = v[0] - bf2f(h0), r1 = v[1] - bf2f(h1);
        u16 l0 = f2bf_bits(r0), l1 = f2bf_bits(r1);
        g_BpHi[(ky * 16 + p) * 24 + oc] = (u32)h0 | ((u32)h1 << 16);
        g_BpLo[(ky * 16 + p) * 24 + oc] = (u32)l0 | ((u32)l1 << 16);
    }
}

// Fold kernel: permuted 1x1 conv fold
__global__ void k_Wq(const float* __restrict__ p_w) {
    int idx = blockIdx.x * blockDim.x + threadIdx.x;
    if (idx >= 1000) return;
    int o = idx / 100, p = idx % 100;
    float s0 = 0.f;
    for (int j = 0; j < 14; j++) {
        float wf = g_Wf[o * 1400 + j * 100 + p];
        s0 += wf * p_w[j * 3 + 0];
        g_Wq[o * 2900 + (2 * j + 1) * 100 + p] = wf * p_w[j * 3 + 1];
        g_Wq[o * 2900 + (2 * j + 2) * 100 + p] = wf * p_w[j * 3 + 2];
    }
    g_Wq[o * 2900 + p] = s0;
}

// Fold kernel: conv3 fold into M[2880][10]
__global__ void k_M(const float* __restrict__ w3) {
    int idx = blockIdx.x * blockDim.x + threadIdx.x;
    if (idx >= 28800) return;
    int o = idx / 2880, k = idx % 2880;
    int ci = k / 144;
    int iy = (k % 144) / 12;
    int ix = k % 12;
    float val = 0.f;
    for (int co = 0; co < 29; co++) {
        for (int ky = 0; ky < 3; ky++) {
            int oy = iy - ky;
            if (oy < 0 || oy >= 10) continue;
            for (int kx = 0; kx < 3; kx++) {
                int ox = ix - kx;
                if (ox < 0 || ox >= 10) continue;
                val += g_Wq[o * 2900 + co * 100 + oy * 10 + ox] *
                       w3[((co * 20 + ci) * 3 + ky) * 3 + kx];
            }
        }
    }
    g_M[k * 10 + o] = val;
}

// Fold kernel: final bias
__global__ void k_cbias(const float* __restrict__ fc1_b, const float* __restrict__ fc2_w,
                        const float* __restrict__ fc2_b, const float* __restrict__ fc3_w,
                        const float* __restrict__ fc3_b, const float* __restrict__ p_b,
                        const float* __restrict__ conv3_b) {
    int o = threadIdx.x;
    if (o >= 10) return;
    float bf = fc3_b[o];
    for (int j = 0; j < 84; j++) {
        float t = fc2_b[j];
        for (int i = 0; i < 120; i++) t += fc2_w[j * 120 + i] * fc1_b[i];
        bf += fc3_w[o * 84 + j] * t;
    }
    for (int j = 0; j < 14; j++) {
        float s = 0.f;
        for (int p = 0; p < 100; p++) s += g_Wf[o * 1400 + j * 100 + p];
        bf += p_b[j] * s;
    }
    for (int co = 0; co < 29; co++) {
        float s = 0.f;
        for (int p = 0; p < 100; p++) s += g_Wq[o * 2900 + co * 100 + p];
        bf += conv3_b[co] * s;
    }
    g_cbias[o] = bf;
}

// ---------------------------------------------------------------------------
// Main kernel: 1 CTA = 1 image, 288 threads (9 warps).
// smem layout (dynamic):
//   [0, 27648)       image bf16: hiE(3x2304) hiO(3x2304) loE loO  (LO at +13824)
//                    plane: 32 rows x 36 bf16 (72B row stride); O copy shifted by 1 px
//   [27648, 55296)   weight pairs: hi 3456 u32, lo 3456 u32 (LO at +13824)
//   [55296, 110592)  conv output fp32 [576 pos][24 oc]
//   [110592, 110976) reduction scratch
// ---------------------------------------------------------------------------
#define XS_OFF   0
#define LO_OFF   13824
#define BP_OFF   27648
#define CONV_OFF 55296
#define RED_OFF  110592
#define SMEM_TOT 110976

__global__ void __launch_bounds__(288, 2) k_main(const float* __restrict__ x,
                                                 float* __restrict__ out) {
    extern __shared__ char sm[];
    int tid = threadIdx.x;
    int b = blockIdx.x;

    // ---- zero image region, load weight pair tables ----
    u32* smu = (u32*)sm;
    for (int i = tid; i < 6912; i += 288) smu[i] = 0u;
    for (int i = tid; i < 3456; i += 288) {
        *(u32*)(sm + BP_OFF + i * 4) = g_BpHi[i];
        *(u32*)(sm + BP_OFF + LO_OFF + i * 4) = g_BpLo[i];
    }
    __syncthreads();

    // ---- convert image to bf16 hi/lo, even + odd-shifted copies ----
    const float* xb = x + (size_t)b * 3072;
    for (int i = tid; i < 3072; i += 288) {
        float v = xb[i];
        int ic = i >> 10, rem = i & 1023;
        int y = rem >> 5, xp = rem & 31;
        u16 hb = f2bf_bits(v);
        u16 lb = f2bf_bits(v - bf2f(hb));
        int rowE = ic * 2304 + y * 72;
        *(u16*)(sm + rowE + xp * 2) = hb;
        *(u16*)(sm + rowE + LO_OFF + xp * 2) = lb;
        if (xp >= 1) {
            *(u16*)(sm + rowE + 6912 + (xp - 1) * 2) = hb;
            *(u16*)(sm + rowE + 6912 + LO_OFF + (xp - 1) * 2) = lb;
        }
    }
    __syncthreads();

    // ---- tensor-core conv: M=576 pos, N=24 oc, K=9ky x 32 ----
    int lane = tid & 31;
    int warp = tid >> 5;            // 0..8, owns m-tiles 4w..4w+3
    int g = lane >> 2;              // group id (row within tile)
    int tig = lane & 3;

    // per-m-tile row bases (parity-selected E/O copy, cx folded in)
    int mbase0[4], mbase1[4];
#pragma unroll
    for (int mi = 0; mi < 4; mi++) {
        int t = warp * 4 + mi;
        int p0 = t * 16 + g;
        int p1 = p0 + 8;
        int cy0 = p0 / 24, cx0 = p0 % 24;
        int cy1 = p1 / 24, cx1 = p1 % 24;
        mbase0[mi] = ((cx0 & 1) ? 6912 + (cx0 - 1) * 2 : cx0 * 2) + cy0 * 72;
        mbase1[mi] = ((cx1 & 1) ? 6912 + (cx1 - 1) * 2 : cx1 * 2) + cy1 * 72;
    }

    // A-pair deltas: dA[s][e], k'' = s*16 + 2*tig + 8*e
    int dA[2][2];
#pragma unroll
    for (int s = 0; s < 2; s++)
#pragma unroll
        for (int e = 0; e < 2; e++) {
            int k2 = s * 16 + tig * 2 + e * 8;
            dA[s][e] = (k2 < 30) ? (k2 / 10) * 2304 + (k2 % 10) * 2 : 0;
        }

    // B deltas: dB[nt][reg]
    int dB[3][2];
#pragma unroll
    for (int nt = 0; nt < 3; nt++)
#pragma unroll
        for (int r = 0; r < 2; r++)
            dB[nt][r] = (tig + r * 4) * 96 + (nt * 8 + g) * 4;

    float d[4][3][4];
#pragma unroll
    for (int mi = 0; mi < 4; mi++)
#pragma unroll
        for (int nt = 0; nt < 3; nt++)
#pragma unroll
            for (int r = 0; r < 4; r++) d[mi][nt][r] = 0.f;

#pragma unroll 1
    for (int ky = 0; ky < 9; ky++) {
        int kyoff = ky * 72;
        int bk = BP_OFF + ky * 1536;
#pragma unroll
        for (int s = 0; s < 2; s++) {
            int bks = bk + s * 768;
            u32 bh[3][2], bl[3][2];
#pragma unroll
            for (int nt = 0; nt < 3; nt++)
#pragma unroll
                for (int r = 0; r < 2; r++) {
                    int addr = bks + dB[nt][r];
                    bh[nt][r] = *(const u32*)(sm + addr);
                    bl[nt][r] = *(const u32*)(sm + addr + LO_OFF);
                }
#pragma unroll
            for (int mi = 0; mi < 4; mi++) {
                int r0 = mbase0[mi] + kyoff;
                int r1 = mbase1[mi] + kyoff;
                int ad0 = r0 + dA[s][0];
                int ad1 = r1 + dA[s][0];
                int ad2 = r0 + dA[s][1];
                int ad3 = r1 + dA[s][1];
                u32 ah[4], al[4];
                ah[0] = *(const u32*)(sm + ad0);
                ah[1] = *(const u32*)(sm + ad1);
                ah[2] = *(const u32*)(sm + ad2);
                ah[3] = *(const u32*)(sm + ad3);
                al[0] = *(const u32*)(sm + ad0 + LO_OFF);
                al[1] = *(const u32*)(sm + ad1 + LO_OFF);
                al[2] = *(const u32*)(sm + ad2 + LO_OFF);
                al[3] = *(const u32*)(sm + ad3 + LO_OFF);
#pragma unroll
                for (int nt = 0; nt < 3; nt++) {
                    mma16816(d[mi][nt], ah, bh[nt][0], bh[nt][1]);  // hi*hi
                    mma16816(d[mi][nt], ah, bl[nt][0], bl[nt][1]);  // hi*lo
                    mma16816(d[mi][nt], al, bh[nt][0], bh[nt][1]);  // lo*hi
                }
            }
        }
    }

    // ---- store conv outputs to smem ----
#pragma unroll
    for (int mi = 0; mi < 4; mi++) {
        int t = warp * 4 + mi;
        int p0 = t * 16 + g;
        int p1 = p0 + 8;
#pragma unroll
        for (int nt = 0; nt < 3; nt++) {
            int col = nt * 8 + tig * 2;
            *(float2*)(sm + CONV_OFF + p0 * 96 + col * 4) =
                make_float2(d[mi][nt][0], d[mi][nt][1]);
            *(float2*)(sm + CONV_OFF + p1 * 96 + col * 4) =
                make_float2(d[mi][nt][2], d[mi][nt][3]);
        }
    }
    __syncthreads();

    // ---- epilogue: bias + 2x2 maxpool + dot with folded M ----
    const float* cv = (const float*)(sm + CONV_OFF);
    int pos = tid % 144;
    int grp = tid / 144;
    int py = pos / 12, px = pos % 12;
    int p00 = (py * 2) * 24 + px * 2;

    float po[10];
#pragma unroll
    for (int c = 0; c < 10; c++) {
        int ch = grp * 10 + c;
        float v00 = cv[p00 * 24 + ch];
        float v01 = cv[(p00 + 1) * 24 + ch];
        float v10 = cv[(p00 + 24) * 24 + ch];
        float v11 = cv[(p00 + 25) * 24 + ch];
        po[c] = fmaxf(fmaxf(v00, v01), fmaxf(v10, v11)) + g_bc[ch];
    }

    float oa[10];
#pragma unroll
    for (int o = 0; o < 10; o++) oa[o] = 0.f;
#pragma unroll 1
    for (int c = 0; c < 10; c++) {
        const float* Mr = &g_M[((grp * 10 + c) * 144 + pos) * 10];
        float p = po[c];
#pragma unroll
        for (int o = 0; o < 10; o++) oa[o] += Mr[o] * p;
    }

#pragma unroll
    for (int o = 0; o < 10; o++) {
#pragma unroll
        for (int off = 16; off > 0; off >>= 1)
            oa[o] += __shfl_xor_sync(0xffffffffu, oa[o], off);
    }
    float* red = (float*)(sm + RED_OFF);
    if ((tid & 31) == 0) {
#pragma unroll
        for (int o = 0; o < 10; o++) red[warp * 10 + o] = oa[o];
    }
    __syncthreads();
    if (tid < 10) {
        float s = g_cbias[tid];
#pragma unroll
        for (int w = 0; w < 9; w++) s += red[w * 10 + tid];
        out[(size_t)b * 10 + tid] = s;
    }
}

// ---------------------------------------------------------------------------
extern "C" void kernel_launch(void* const* d_in, const int* in_sizes, int n_in,
                              void* d_out, int out_size) {
    const float* x       = (const float*)d_in[0];
    const float* conv1_w = (const float*)d_in[1];
    const float* conv1_b = (const float*)d_in[2];
    const float* conv2_w = (const float*)d_in[3];
    const float* conv2_b = (const float*)d_in[4];
    const float* conv3_w = (const float*)d_in[5];
    const float* conv3_b = (const float*)d_in[6];
    const float* p_w     = (const float*)d_in[7];
    const float* p_b     = (const float*)d_in[8];
    const float* fc1_w   = (const float*)d_in[9];
    const float* fc1_b   = (const float*)d_in[10];
    const float* fc2_w   = (const float*)d_in[11];
    const float* fc2_b   = (const float*)d_in[12];
    const float* fc3_w   = (const float*)d_in[13];
    const float* fc3_b   = (const float*)d_in[14];
    float* out = (float*)d_out;

    int nb = in_sizes[0] / 3072;

    static int configured = 0;
    if (!configured) {
        cudaFuncSetAttribute(k_main, cudaFuncAttributeMaxDynamicSharedMemorySize, SMEM_TOT);
        configured = 1;
    }

    // exactly 5 fold launches so ncu (-s 5 -c 1) profiles k_main
    kA_T_combine<<<(117600 + 4880 + 255) / 256, 256>>>(fc1_w, fc2_w, conv1_w, conv1_b,
                                                       conv2_w, conv2_b);
    kB_Wf_Bpair<<<(14000 + 3456 + 255) / 256, 256>>>(fc3_w);
    k_Wq<<<4, 256>>>(p_w);
    k_M<<<(28800 + 255) / 256, 256>>>(conv3_w);
    k_cbias<<<1, 32>>>(fc1_b, fc2_w, fc2_b, fc3_w, fc3_b, p_b, conv3_b);
    k_main<<<nb, 288, SMEM_TOT>>>(x, out);
}